// round 13
// baseline (speedup 1.0000x reference)
#include <cuda_runtime.h>
#include <cuda_fp16.h>
#include <cstdint>

#define BBATCH 8
#define CCH    28
#define HHH    256
#define WWW    256
#define KHH    7
#define NGI    49
#define HW     (HHH*WWW)
#define PADH   3

// smem u32-index layout
#define BF_OFF    0
#define BF_U32    3584
#define MIDH_OFF  (BF_OFF+BF_U32)      // 16 pair-rows x 264 = 4224
#define STG_OFF   (MIDH_OFF+4224)      // 8 warps x 2 buf x 320 = 5120
#define TBL_OFF   (STG_OFF+5120)
#define SMEM_U32  (TBL_OFF + 56*6 + 64 + 16)
#define SMEM_BYTES (SMEM_U32*4)
// epilogue-2 bounce buffer: 28 rows x 260 fp32 = 7280 u32, reuses [0, 7280) (< STG_OFF)

// precomputed weight tables (setup kernel -> main kernel)
__device__ uint32_t d_b1p[NGI * 64];   // [gi][cp(2)][n(32)] packed half2
__device__ uint4    d_b2f[896];        // stage-2 B fragments

static __device__ __forceinline__ void mma16(float* d,
                                             uint32_t a0, uint32_t a1,
                                             uint32_t a2, uint32_t a3,
                                             uint32_t b0, uint32_t b1) {
    asm volatile(
        "mma.sync.aligned.m16n8k16.row.col.f32.f16.f16.f32 "
        "{%0,%1,%2,%3}, {%4,%5,%6,%7}, {%8,%9}, {%0,%1,%2,%3};"
        : "+f"(d[0]), "+f"(d[1]), "+f"(d[2]), "+f"(d[3])
        : "r"(a0), "r"(a1), "r"(a2), "r"(a3), "r"(b0), "r"(b1));
}
static __device__ __forceinline__ uint32_t h2u(__half2 h) {
    return *reinterpret_cast<uint32_t*>(&h);
}

// ---------------------------------------------------------------------------
// Setup: per-tap B1 half2 table + full B2 fragment array (h-independent).
// ---------------------------------------------------------------------------
__global__ void setup_bfrag_kernel(const float* __restrict__ weight,
                                   const float* __restrict__ w_t,
                                   const float* __restrict__ w_m) {
    int idx = blockIdx.x * blockDim.x + threadIdx.x;
    if (idx < NGI * 64) {
        int gi = idx >> 6;
        int cp = (idx >> 5) & 1;
        int n  = idx & 31;
        float va = 0.0f, vb = 0.0f;
        if (n < CCH) {
            int gc = (gi / KHH) * 4, ki = gi % KHH;
            va = weight[(n * CCH + gc + 2 * cp) * KHH + ki];
            vb = weight[(n * CCH + gc + 2 * cp + 1) * KHH + ki];
        }
        d_b1p[idx] = h2u(__floats2half2_rn(va, vb));
    }
    if (idx < 896) {
        int s  = idx >> 6;
        int np = (idx >> 5) & 1;
        int ln = idx & 31;
        int na = (2 * np) * 8 + (ln >> 2);
        int nb = na + 8;
        int tt = ln & 3;
        int j  = s >> 1;
        int ie = 8 * (s & 1) + tt;
        uint32_t u[4];
        #pragma unroll
        for (int e = 0; e < 4; ++e) {
            int n  = (e >> 1) ? nb : na;
            int i0 = ie + 4 * (e & 1);
            float va = 0.0f, vb = 0.0f;
            if (n < CCH) {
                int f = n >> 2, cq = n & 3;
                #pragma unroll
                for (int g7 = 0; g7 < 7; ++g7) {
                    float wm = w_m[f * 7 + g7];
                    int base = (g7 * 4 + cq) * CCH;
                    if (i0 < CCH)      va += wm * w_t[(base + i0) * KHH + j];
                    if (i0 + 16 < CCH) vb += wm * w_t[(base + i0 + 16) * KHH + j];
                }
            }
            u[e] = h2u(__floats2half2_rn(va, vb));
        }
        d_b2f[idx] = make_uint4(u[0], u[1], u[2], u[3]);
    }
}

// ---------------------------------------------------------------------------
__global__ void __launch_bounds__(256, 4)
harmonic_mma_kernel(const float* __restrict__ x,
                    const float* __restrict__ bias,
                    const float* __restrict__ b_t,
                    const float* __restrict__ w_m,
                    const float* __restrict__ b_m,
                    float* __restrict__ out) {
    extern __shared__ uint32_t smu[];
    uint32_t* s_bf  = smu + BF_OFF;
    uint32_t* s_mhi = smu + MIDH_OFF;
    uint32_t* s_stg = smu + STG_OFF;
    float*    s_f0  = (float*)(smu + TBL_OFF);
    float*    s_f1  = s_f0 + 56;
    int*      s_y0  = (int*)(s_f1 + 56);
    int*      s_y1  = s_y0 + 56;
    int*      s_pl  = s_y1 + 56;
    int*      s_gi  = s_pl + 56;
    float*    s_b1  = (float*)(s_gi + 56);
    float*    s_B2  = s_b1 + 32;
    int*      s_ns  = (int*)(s_B2 + 32);

    const int tid  = threadIdx.x;
    const int wid  = tid >> 5;
    const int lane = tid & 31;
    const int g    = lane >> 2;
    const int tig  = lane & 3;
    const int h    = blockIdx.x & 255;
    const int b    = blockIdx.x >> 8;
    const int mbase = wid * 32;

    // ---- phase A: raw per-h tables (scratch in BF region) ----
    float* r_f0 = (float*)s_bf;
    float* r_f1 = r_f0 + 49;
    int*   r_y0 = (int*)(r_f1 + 49);
    int*   r_y1 = r_y0 + 49;
    if (tid < NGI) {
        int gg = tid / KHH, ii = tid % KHH;
        float fh = (float)h, fg = (float)gg, fi = (float)ii;
        float t   = __fdiv_rn(fh + 1.0f, fg + 1.0f) * (fi + 1.0f);
        float off = -fi + t - (fh + 1.0f);
        float yp  = fh - (float)PADH + fi + off;
        float y0f = floorf(yp);
        float fy  = yp - y0f;
        int   y0i = (int)y0f;
        float v0 = (y0i >= 0 && y0i <= HHH - 1) ? 1.0f : 0.0f;
        float v1 = (y0i + 1 >= 0 && y0i + 1 <= HHH - 1) ? 1.0f : 0.0f;
        int y0c = y0i < 0 ? 0 : (y0i > HHH - 1 ? HHH - 1 : y0i);
        int y1i = y0i + 1;
        int y1c = y1i < 0 ? 0 : (y1i > HHH - 1 ? HHH - 1 : y1i);
        r_y0[tid] = y0c * WWW;
        r_y1[tid] = y1c * WWW;
        r_f0[tid] = (1.0f - fy) * v0;
        r_f1[tid] = fy * v1;
    }
    if (tid < 32) {
        s_b1[tid] = (tid < CCH) ? bias[tid] : 0.0f;
        float s = 0.0f;
        if (tid < CCH) {
            int f = tid >> 2, cq = tid & 3;
            s = b_m[f];
            #pragma unroll
            for (int g7 = 0; g7 < 7; ++g7) s += w_m[f * 7 + g7] * b_t[g7 * 4 + cq];
        }
        s_B2[tid] = s;
    }
    if (tid < 128) {
        int p = tid >> 3, c8 = tid & 7;
        int col = (c8 < 3) ? c8 : 256 + c8;
        s_mhi[p * 264 + col] = 0u;
    }
    __syncthreads();

    // ---- phase B: compact live taps ----
    if (tid == 0) {
        int nl = 0;
        for (int gi = 0; gi < NGI; ++gi) {
            float f0 = r_f0[gi], f1 = r_f1[gi];
            if (f0 != 0.0f || f1 != 0.0f) {
                s_f0[nl] = f0; s_f1[nl] = f1;
                s_y0[nl] = r_y0[gi]; s_y1[nl] = r_y1[gi];
                s_pl[nl] = (gi / KHH) * 4;
                s_gi[nl] = gi;
                ++nl;
            }
        }
        int ns1 = (nl + 3) >> 2;
        for (int p = nl; p < ns1 * 4; ++p) {
            s_f0[p] = 0.0f; s_f1[p] = 0.0f;
            s_y0[p] = 0;    s_y1[p] = 0;
            s_pl[p] = 0;    s_gi[p] = -1;
        }
        *s_ns = ns1;
    }
    __syncthreads();
    const int ns1 = *s_ns;

    // ---- B1 fragments from precomputed per-tap table ----
    for (int idx = tid; idx < ns1 * 64; idx += 256) {
        int s  = idx >> 6;
        int np = (idx >> 5) & 1;
        int ln = idx & 31;
        int na = 16 * np + (ln >> 2);
        int tt = ln & 3;
        int cpo = (tt & 1) * 32;
        int sb = 4 * s + (tt >> 1);
        int ga = s_gi[sb], gb = s_gi[sb + 2];
        uint32_t u0 = 0, u1 = 0, u2 = 0, u3 = 0;
        if (ga >= 0) {
            u0 = d_b1p[ga * 64 + cpo + na];
            u2 = d_b1p[ga * 64 + cpo + na + 8];
        }
        if (gb >= 0) {
            u1 = d_b1p[gb * 64 + cpo + na];
            u3 = d_b1p[gb * 64 + cpo + na + 8];
        }
        ((uint4*)s_bf)[idx] = make_uint4(u0, u1, u2, u3);
    }
    __syncthreads();

    const float* xb = x + (size_t)b * CCH * HW;

    float acc[2][4][4];
    #pragma unroll
    for (int t = 0; t < 2; ++t)
        #pragma unroll
        for (int nt = 0; nt < 4; ++nt)
            #pragma unroll
            for (int r = 0; r < 4; ++r) acc[t][nt][r] = 0.0f;

    // ======= STAGE 1 : ns1 k16 steps, single-A-term, predicated gather =======
    #pragma unroll 1
    for (int s = 0; s < ns1; ++s) {
        uint32_t* stb = s_stg + wid * 640 + (s & 1) * 320;   // double-buffered
        #pragma unroll
        for (int r = 0; r < 2; ++r) {
            #pragma unroll
            for (int tp = 0; tp < 2; ++tp) {
                const int sl = 4 * s + 2 * r + tp;
                const int o0 = s_y0[sl], o1 = s_y1[sl];
                const float f0 = s_f0[sl], f1 = s_f1[sl];
                const bool p0 = (f0 != 0.0f);
                const bool p1 = (f1 != 0.0f);
                const float* pp = xb + (size_t)s_pl[sl] * HW + mbase + lane;
                float vv[4];
                #pragma unroll
                for (int c = 0; c < 4; ++c) {
                    float a0 = p0 ? __ldg(pp + c * HW + o0) : 0.0f;
                    float a1 = p1 ? __ldg(pp + c * HW + o1) : 0.0f;
                    vv[c] = a0 * f0 + a1 * f1;
                }
                int kp = 4 * r + 2 * tp;
                stb[kp * 40 + lane]       = h2u(__floats2half2_rn(vv[0], vv[1]));
                stb[(kp + 1) * 40 + lane] = h2u(__floats2half2_rn(vv[2], vv[3]));
            }
        }
        __syncwarp();

        uint32_t ahi[2][4];
        #pragma unroll
        for (int t = 0; t < 2; ++t) {
            int mb2 = 16 * t + g;
            ahi[t][0] = stb[tig * 40 + mb2];
            ahi[t][1] = stb[tig * 40 + mb2 + 8];
            ahi[t][2] = stb[(tig + 4) * 40 + mb2];
            ahi[t][3] = stb[(tig + 4) * 40 + mb2 + 8];
        }
        // no second syncwarp: next iteration writes the other staging buffer

        const uint4* bfp = (const uint4*)s_bf + s * 64 + lane;
        #pragma unroll
        for (int np = 0; np < 2; ++np) {
            uint4 bv = bfp[np * 32];
            #pragma unroll
            for (int t = 0; t < 2; ++t) {
                mma16(acc[t][2*np],   ahi[t][0], ahi[t][1], ahi[t][2], ahi[t][3], bv.x, bv.y);
                mma16(acc[t][2*np+1], ahi[t][0], ahi[t][1], ahi[t][2], ahi[t][3], bv.z, bv.w);
            }
        }
    }

    // ---- epilogue 1: acc -> mid fp16x2 plane (+bias) ----
    #pragma unroll
    for (int t = 0; t < 2; ++t) {
        #pragma unroll
        for (int nt = 0; nt < 2; ++nt) {
            #pragma unroll
            for (int r = 0; r < 4; ++r) {
                int n   = nt * 8 + 2 * tig + (r & 1);
                int row = mbase + 16 * t + g + 8 * (r >> 1);
                float va = acc[t][nt][r]     + s_b1[n];
                float vb = acc[t][nt + 2][r] + s_b1[n + 16];
                s_mhi[n * 264 + 3 + row] = h2u(__floats2half2_rn(va, vb));
            }
        }
    }
    __syncthreads();

    // ---- B2 fragments: straight copy from precomputed global ----
    for (int idx = tid; idx < 896; idx += 256)
        ((uint4*)s_bf)[idx] = d_b2f[idx];
    #pragma unroll
    for (int t = 0; t < 2; ++t)
        #pragma unroll
        for (int nt = 0; nt < 4; ++nt)
            #pragma unroll
            for (int r = 0; r < 4; ++r) acc[t][nt][r] = 0.0f;
    __syncthreads();

    // =================== STAGE 2 : 14 k16 steps, single-A-term ================
    #pragma unroll 2
    for (int s = 0; s < 14; ++s) {
        const int j  = s >> 1;
        const int p0 = 8 * (s & 1) + tig;
        const int cb = mbase + g + j;
        uint32_t ahi[2][4];
        #pragma unroll
        for (int t = 0; t < 2; ++t) {
            int c0 = cb + 16 * t;
            ahi[t][0] = s_mhi[p0 * 264 + c0];
            ahi[t][1] = s_mhi[p0 * 264 + c0 + 8];
            ahi[t][2] = s_mhi[(p0 + 4) * 264 + c0];
            ahi[t][3] = s_mhi[(p0 + 4) * 264 + c0 + 8];
        }
        const uint4* bfp = (const uint4*)s_bf + s * 64 + lane;
        #pragma unroll
        for (int np = 0; np < 2; ++np) {
            uint4 bv = bfp[np * 32];
            #pragma unroll
            for (int t = 0; t < 2; ++t) {
                mma16(acc[t][2*np],   ahi[t][0], ahi[t][1], ahi[t][2], ahi[t][3], bv.x, bv.y);
                mma16(acc[t][2*np+1], ahi[t][0], ahi[t][1], ahi[t][2], ahi[t][3], bv.z, bv.w);
            }
        }
    }

    // ---- epilogue 2: acc -> smem bounce (stride 260) -> coalesced float4 STG --
    __syncthreads();                       // all warps done reading s_mhi/s_bf
    float* s_out = (float*)smu;            // reuse [0, 7280) u32
    #pragma unroll
    for (int t = 0; t < 2; ++t) {
        int r0 = mbase + 16 * t + g;
        #pragma unroll
        for (int nt = 0; nt < 4; ++nt) {
            int n0 = nt * 8 + tig * 2;
            int n1 = n0 + 1;
            if (n0 < CCH) {
                float bq = s_B2[n0];
                s_out[n0 * 260 + r0]     = acc[t][nt][0] + bq;
                s_out[n0 * 260 + r0 + 8] = acc[t][nt][2] + bq;
            }
            if (n1 < CCH) {
                float bq = s_B2[n1];
                s_out[n1 * 260 + r0]     = acc[t][nt][1] + bq;
                s_out[n1 * 260 + r0 + 8] = acc[t][nt][3] + bq;
            }
        }
    }
    __syncthreads();

    float* ob2 = out + (size_t)b * CCH * HW + h * WWW;
    #pragma unroll
    for (int k = 0; k < 7; ++k) {
        int idx = tid + 256 * k;           // 0..1791 float4s
        int n   = idx >> 6;
        int w4  = (idx & 63) << 2;
        float4 v = *(float4*)(s_out + n * 260 + w4);
        *(float4*)(ob2 + (size_t)n * HW + w4) = v;
    }
}

// ---------------------------------------------------------------------------
extern "C" void kernel_launch(void* const* d_in, const int* in_sizes, int n_in,
                              void* d_out, int out_size) {
    const float* x      = (const float*)d_in[0];
    const float* weight = (const float*)d_in[1];
    const float* bias   = (const float*)d_in[2];
    const float* w_t    = (const float*)d_in[3];
    const float* b_t    = (const float*)d_in[4];
    const float* w_m    = (const float*)d_in[5];
    const float* b_m    = (const float*)d_in[6];
    float* out = (float*)d_out;

    setup_bfrag_kernel<<<(NGI * 64 + 255) / 256, 256>>>(weight, w_t, w_m);

    cudaFuncSetAttribute(harmonic_mma_kernel,
                         cudaFuncAttributeMaxDynamicSharedMemorySize, SMEM_BYTES);
    harmonic_mma_kernel<<<BBATCH * HHH, 256, SMEM_BYTES>>>(
        x, bias, b_t, w_m, b_m, out);
}

// round 14
// speedup vs baseline: 1.0981x; 1.0981x over previous
#include <cuda_runtime.h>
#include <cuda_fp16.h>
#include <cstdint>

#define BBATCH 8
#define CCH    28
#define HHH    256
#define WWW    256
#define KHH    7
#define NGI    49
#define HW     (HHH*WWW)
#define PADH   3

// smem u32-index layout (same as R12)
#define BF_OFF    0
#define BF_U32    3584
#define MIDH_OFF  (BF_OFF+BF_U32)      // 16 pair-rows x 264 = 4224
#define STG_OFF   (MIDH_OFF+4224)      // 8 warps x 320
#define TBL_OFF   (STG_OFF+2560)
#define SMEM_U32  (TBL_OFF + 56*5 + 64 + 16)
#define SMEM_BYTES (SMEM_U32*4)

// precomputed tables (setup kernels -> main kernel)
__device__ uint32_t d_b1p[NGI * 64];        // [gi][cp(2)][n(32)] packed half2
__device__ uint4    d_b2f[896];             // stage-2 B fragments
__device__ float    d_tf0[HHH * 56];        // per-h compacted tap tables
__device__ float    d_tf1[HHH * 56];
__device__ int      d_ty0[HHH * 56];
__device__ int      d_ty1[HHH * 56];
__device__ int      d_tpl[HHH * 56];
__device__ int      d_tns[HHH];
__device__ uint4    d_b1f[HHH * 896];       // per-h stage-1 B fragments

static __device__ __forceinline__ void mma16(float* d,
                                             uint32_t a0, uint32_t a1,
                                             uint32_t a2, uint32_t a3,
                                             uint32_t b0, uint32_t b1) {
    asm volatile(
        "mma.sync.aligned.m16n8k16.row.col.f32.f16.f16.f32 "
        "{%0,%1,%2,%3}, {%4,%5,%6,%7}, {%8,%9}, {%0,%1,%2,%3};"
        : "+f"(d[0]), "+f"(d[1]), "+f"(d[2]), "+f"(d[3])
        : "r"(a0), "r"(a1), "r"(a2), "r"(a3), "r"(b0), "r"(b1));
}
static __device__ __forceinline__ uint32_t h2u(__half2 h) {
    return *reinterpret_cast<uint32_t*>(&h);
}

// ---------------------------------------------------------------------------
// Setup 1: weight-derived tables (h-independent).
// ---------------------------------------------------------------------------
__global__ void setup_bfrag_kernel(const float* __restrict__ weight,
                                   const float* __restrict__ w_t,
                                   const float* __restrict__ w_m) {
    int idx = blockIdx.x * blockDim.x + threadIdx.x;
    if (idx < NGI * 64) {
        int gi = idx >> 6;
        int cp = (idx >> 5) & 1;
        int n  = idx & 31;
        float va = 0.0f, vb = 0.0f;
        if (n < CCH) {
            int gc = (gi / KHH) * 4, ki = gi % KHH;
            va = weight[(n * CCH + gc + 2 * cp) * KHH + ki];
            vb = weight[(n * CCH + gc + 2 * cp + 1) * KHH + ki];
        }
        d_b1p[idx] = h2u(__floats2half2_rn(va, vb));
    }
    if (idx < 896) {
        int s  = idx >> 6;
        int np = (idx >> 5) & 1;
        int ln = idx & 31;
        int na = (2 * np) * 8 + (ln >> 2);
        int nb = na + 8;
        int tt = ln & 3;
        int j  = s >> 1;
        int ie = 8 * (s & 1) + tt;
        uint32_t u[4];
        #pragma unroll
        for (int e = 0; e < 4; ++e) {
            int n  = (e >> 1) ? nb : na;
            int i0 = ie + 4 * (e & 1);
            float va = 0.0f, vb = 0.0f;
            if (n < CCH) {
                int f = n >> 2, cq = n & 3;
                #pragma unroll
                for (int g7 = 0; g7 < 7; ++g7) {
                    float wm = w_m[f * 7 + g7];
                    int base = (g7 * 4 + cq) * CCH;
                    if (i0 < CCH)      va += wm * w_t[(base + i0) * KHH + j];
                    if (i0 + 16 < CCH) vb += wm * w_t[(base + i0 + 16) * KHH + j];
                }
            }
            u[e] = h2u(__floats2half2_rn(va, vb));
        }
        d_b2f[idx] = make_uint4(u[0], u[1], u[2], u[3]);
    }
}

// ---------------------------------------------------------------------------
// Setup 2: per-h compacted tap tables + per-h B1 fragments. One block per h.
// ---------------------------------------------------------------------------
__global__ void setup_perh_kernel() {
    __shared__ float r_f0[49], r_f1[49];
    __shared__ int   r_y0[49], r_y1[49];
    __shared__ int   c_gi[56];
    __shared__ int   sh_ns;

    const int h   = blockIdx.x;
    const int tid = threadIdx.x;

    if (tid < NGI) {
        int gg = tid / KHH, ii = tid % KHH;
        float fh = (float)h, fg = (float)gg, fi = (float)ii;
        float t   = __fdiv_rn(fh + 1.0f, fg + 1.0f) * (fi + 1.0f);
        float off = -fi + t - (fh + 1.0f);
        float yp  = fh - (float)PADH + fi + off;
        float y0f = floorf(yp);
        float fy  = yp - y0f;
        int   y0i = (int)y0f;
        float v0 = (y0i >= 0 && y0i <= HHH - 1) ? 1.0f : 0.0f;
        float v1 = (y0i + 1 >= 0 && y0i + 1 <= HHH - 1) ? 1.0f : 0.0f;
        int y0c = y0i < 0 ? 0 : (y0i > HHH - 1 ? HHH - 1 : y0i);
        int y1i = y0i + 1;
        int y1c = y1i < 0 ? 0 : (y1i > HHH - 1 ? HHH - 1 : y1i);
        r_y0[tid] = y0c * WWW;
        r_y1[tid] = y1c * WWW;
        r_f0[tid] = (1.0f - fy) * v0;
        r_f1[tid] = fy * v1;
    }
    __syncthreads();

    if (tid == 0) {
        int nl = 0;
        for (int gi = 0; gi < NGI; ++gi) {
            if (r_f0[gi] != 0.0f || r_f1[gi] != 0.0f) {
                d_tf0[h * 56 + nl] = r_f0[gi];
                d_tf1[h * 56 + nl] = r_f1[gi];
                d_ty0[h * 56 + nl] = r_y0[gi];
                d_ty1[h * 56 + nl] = r_y1[gi];
                d_tpl[h * 56 + nl] = (gi / KHH) * 4;
                c_gi[nl] = gi;
                ++nl;
            }
        }
        int ns1 = (nl + 3) >> 2;
        for (int p = nl; p < ns1 * 4; ++p) {
            d_tf0[h * 56 + p] = 0.0f;
            d_tf1[h * 56 + p] = 0.0f;
            d_ty0[h * 56 + p] = 0;
            d_ty1[h * 56 + p] = 0;
            d_tpl[h * 56 + p] = 0;
            c_gi[p] = -1;
        }
        d_tns[h] = ns1;
        sh_ns = ns1;
    }
    __syncthreads();
    const int ns1 = sh_ns;

    // per-h B1 fragments (same indexing as R12's in-kernel fill)
    for (int idx = tid; idx < ns1 * 64; idx += blockDim.x) {
        int s  = idx >> 6;
        int np = (idx >> 5) & 1;
        int ln = idx & 31;
        int na = 16 * np + (ln >> 2);
        int tt = ln & 3;
        int cpo = (tt & 1) * 32;
        int sb = 4 * s + (tt >> 1);
        int ga = c_gi[sb], gb = c_gi[sb + 2];
        uint32_t u0 = 0, u1 = 0, u2 = 0, u3 = 0;
        if (ga >= 0) {
            u0 = d_b1p[ga * 64 + cpo + na];
            u2 = d_b1p[ga * 64 + cpo + na + 8];
        }
        if (gb >= 0) {
            u1 = d_b1p[gb * 64 + cpo + na];
            u3 = d_b1p[gb * 64 + cpo + na + 8];
        }
        d_b1f[h * 896 + idx] = make_uint4(u0, u1, u2, u3);
    }
}

// ---------------------------------------------------------------------------
__global__ void __launch_bounds__(256, 4)
harmonic_mma_kernel(const float* __restrict__ x,
                    const float* __restrict__ bias,
                    const float* __restrict__ b_t,
                    const float* __restrict__ w_m,
                    const float* __restrict__ b_m,
                    float* __restrict__ out) {
    extern __shared__ uint32_t smu[];
    uint32_t* s_bf  = smu + BF_OFF;
    uint32_t* s_mhi = smu + MIDH_OFF;
    uint32_t* s_stg = smu + STG_OFF;
    float*    s_f0  = (float*)(smu + TBL_OFF);
    float*    s_f1  = s_f0 + 56;
    int*      s_y0  = (int*)(s_f1 + 56);
    int*      s_y1  = s_y0 + 56;
    int*      s_pl  = s_y1 + 56;
    float*    s_b1  = (float*)(s_pl + 56);
    float*    s_B2  = s_b1 + 32;
    int*      s_ns  = (int*)(s_B2 + 32);

    const int tid  = threadIdx.x;
    const int wid  = tid >> 5;
    const int lane = tid & 31;
    const int g    = lane >> 2;
    const int tig  = lane & 3;
    const int h    = blockIdx.x & 255;
    const int b    = blockIdx.x >> 8;
    const int mbase = wid * 32;

    // ---- prologue: coalesced copies only ----
    if (tid < 56) {
        s_f0[tid] = d_tf0[h * 56 + tid];
        s_f1[tid] = d_tf1[h * 56 + tid];
        s_y0[tid] = d_ty0[h * 56 + tid];
        s_y1[tid] = d_ty1[h * 56 + tid];
        s_pl[tid] = d_tpl[h * 56 + tid];
    }
    if (tid == 0) *s_ns = d_tns[h];
    if (tid < 32) {
        s_b1[tid] = (tid < CCH) ? bias[tid] : 0.0f;
        float s = 0.0f;
        if (tid < CCH) {
            int f = tid >> 2, cq = tid & 3;
            s = b_m[f];
            #pragma unroll
            for (int g7 = 0; g7 < 7; ++g7) s += w_m[f * 7 + g7] * b_t[g7 * 4 + cq];
        }
        s_B2[tid] = s;
    }
    if (tid < 128) {
        int p = tid >> 3, c8 = tid & 7;
        int col = (c8 < 3) ? c8 : 256 + c8;
        s_mhi[p * 264 + col] = 0u;
    }
    __syncthreads();
    const int ns1 = *s_ns;

    // B1 fragments: straight copy of the per-h precomputed array
    for (int idx = tid; idx < ns1 * 64; idx += 256)
        ((uint4*)s_bf)[idx] = d_b1f[h * 896 + idx];
    __syncthreads();

    const float* xb = x + (size_t)b * CCH * HW;
    uint32_t* stgh = s_stg + wid * 320;

    float acc[2][4][4];
    #pragma unroll
    for (int t = 0; t < 2; ++t)
        #pragma unroll
        for (int nt = 0; nt < 4; ++nt)
            #pragma unroll
            for (int r = 0; r < 4; ++r) acc[t][nt][r] = 0.0f;

    // =================== STAGE 1 : ns1 k16 steps, single-A-term ===============
    #pragma unroll 1
    for (int s = 0; s < ns1; ++s) {
        #pragma unroll
        for (int r = 0; r < 2; ++r) {
            float vv[8];
            #pragma unroll
            for (int tp = 0; tp < 2; ++tp) {
                const int sl = 4 * s + 2 * r + tp;
                const int o0 = s_y0[sl], o1 = s_y1[sl];
                const float f0 = s_f0[sl], f1 = s_f1[sl];
                const float* pp = xb + (size_t)s_pl[sl] * HW + mbase + lane;
                #pragma unroll
                for (int c = 0; c < 4; ++c) {
                    float a0 = __ldg(pp + c * HW + o0);
                    float a1 = __ldg(pp + c * HW + o1);
                    vv[tp * 4 + c] = a0 * f0 + a1 * f1;
                }
            }
            #pragma unroll
            for (int tp = 0; tp < 2; ++tp) {
                int kp = 4 * r + 2 * tp;
                stgh[kp * 40 + lane]       = h2u(__floats2half2_rn(vv[4*tp+0], vv[4*tp+1]));
                stgh[(kp + 1) * 40 + lane] = h2u(__floats2half2_rn(vv[4*tp+2], vv[4*tp+3]));
            }
        }
        __syncwarp();

        uint32_t ahi[2][4];
        #pragma unroll
        for (int t = 0; t < 2; ++t) {
            int mb2 = 16 * t + g;
            ahi[t][0] = stgh[tig * 40 + mb2];
            ahi[t][1] = stgh[tig * 40 + mb2 + 8];
            ahi[t][2] = stgh[(tig + 4) * 40 + mb2];
            ahi[t][3] = stgh[(tig + 4) * 40 + mb2 + 8];
        }
        __syncwarp();

        const uint4* bfp = (const uint4*)s_bf + s * 64 + lane;
        #pragma unroll
        for (int np = 0; np < 2; ++np) {
            uint4 bv = bfp[np * 32];
            #pragma unroll
            for (int t = 0; t < 2; ++t) {
                mma16(acc[t][2*np],   ahi[t][0], ahi[t][1], ahi[t][2], ahi[t][3], bv.x, bv.y);
                mma16(acc[t][2*np+1], ahi[t][0], ahi[t][1], ahi[t][2], ahi[t][3], bv.z, bv.w);
            }
        }
    }

    // ---- epilogue 1: acc -> mid fp16x2 plane (+bias) ----
    #pragma unroll
    for (int t = 0; t < 2; ++t) {
        #pragma unroll
        for (int nt = 0; nt < 2; ++nt) {
            #pragma unroll
            for (int r = 0; r < 4; ++r) {
                int n   = nt * 8 + 2 * tig + (r & 1);
                int row = mbase + 16 * t + g + 8 * (r >> 1);
                float va = acc[t][nt][r]     + s_b1[n];
                float vb = acc[t][nt + 2][r] + s_b1[n + 16];
                s_mhi[n * 264 + 3 + row] = h2u(__floats2half2_rn(va, vb));
            }
        }
    }
    __syncthreads();

    // ---- B2 fragments: straight copy from precomputed global ----
    for (int idx = tid; idx < 896; idx += 256)
        ((uint4*)s_bf)[idx] = d_b2f[idx];
    #pragma unroll
    for (int t = 0; t < 2; ++t)
        #pragma unroll
        for (int nt = 0; nt < 4; ++nt)
            #pragma unroll
            for (int r = 0; r < 4; ++r) acc[t][nt][r] = 0.0f;
    __syncthreads();

    // =================== STAGE 2 : 14 k16 steps, single-A-term ================
    #pragma unroll 2
    for (int s = 0; s < 14; ++s) {
        const int j  = s >> 1;
        const int p0 = 8 * (s & 1) + tig;
        const int cb = mbase + g + j;
        uint32_t ahi[2][4];
        #pragma unroll
        for (int t = 0; t < 2; ++t) {
            int c0 = cb + 16 * t;
            ahi[t][0] = s_mhi[p0 * 264 + c0];
            ahi[t][1] = s_mhi[p0 * 264 + c0 + 8];
            ahi[t][2] = s_mhi[(p0 + 4) * 264 + c0];
            ahi[t][3] = s_mhi[(p0 + 4) * 264 + c0 + 8];
        }
        const uint4* bfp = (const uint4*)s_bf + s * 64 + lane;
        #pragma unroll
        for (int np = 0; np < 2; ++np) {
            uint4 bv = bfp[np * 32];
            #pragma unroll
            for (int t = 0; t < 2; ++t) {
                mma16(acc[t][2*np],   ahi[t][0], ahi[t][1], ahi[t][2], ahi[t][3], bv.x, bv.y);
                mma16(acc[t][2*np+1], ahi[t][0], ahi[t][1], ahi[t][2], ahi[t][3], bv.z, bv.w);
            }
        }
    }

    // ---- epilogue 2: acc -> out (+fused bias), direct stores (R12 form) ----
    float* ob = out + (size_t)b * CCH * HW + h * WWW;
    #pragma unroll
    for (int t = 0; t < 2; ++t) {
        int r0 = mbase + 16 * t + g;
        #pragma unroll
        for (int nt = 0; nt < 4; ++nt) {
            int n0 = nt * 8 + tig * 2;
            int n1 = n0 + 1;
            if (n0 < CCH) {
                float bq = s_B2[n0];
                ob[(size_t)n0 * HW + r0]     = acc[t][nt][0] + bq;
                ob[(size_t)n0 * HW + r0 + 8] = acc[t][nt][2] + bq;
            }
            if (n1 < CCH) {
                float bq = s_B2[n1];
                ob[(size_t)n1 * HW + r0]     = acc[t][nt][1] + bq;
                ob[(size_t)n1 * HW + r0 + 8] = acc[t][nt][3] + bq;
            }
        }
    }
}

// ---------------------------------------------------------------------------
extern "C" void kernel_launch(void* const* d_in, const int* in_sizes, int n_in,
                              void* d_out, int out_size) {
    const float* x      = (const float*)d_in[0];
    const float* weight = (const float*)d_in[1];
    const float* bias   = (const float*)d_in[2];
    const float* w_t    = (const float*)d_in[3];
    const float* b_t    = (const float*)d_in[4];
    const float* w_m    = (const float*)d_in[5];
    const float* b_m    = (const float*)d_in[6];
    float* out = (float*)d_out;

    setup_bfrag_kernel<<<(NGI * 64 + 255) / 256, 256>>>(weight, w_t, w_m);
    setup_perh_kernel<<<HHH, 256>>>();

    cudaFuncSetAttribute(harmonic_mma_kernel,
                         cudaFuncAttributeMaxDynamicSharedMemorySize, SMEM_BYTES);
    harmonic_mma_kernel<<<BBATCH * HHH, 256, SMEM_BYTES>>>(
        x, bias, b_t, w_m, b_m, out);
}